// round 13
// baseline (speedup 1.0000x reference)
#include <cuda_runtime.h>
#include <cuda_bf16.h>
#include <cstdint>

#define N_IN    16
#define N_RULES 64
#define TPB     128
#define ROWS    128

#define A_STR   176          // A row stride bytes (80 bf16 slots + pad)
#define BT_STR  112          // B-T row: 48 slots + pad
#define BR_STR  80           // B-RO row: 32 slots + pad

#define OFF_A    0
#define OFF_BT   22528       // 128*176
#define OFF_BR   (OFF_BT + 7168)
#define OFF_LAM  (OFF_BR + 5120)
#define OFF_BIAS (OFF_LAM + 256)
#define OFF_AM   (OFF_BIAS + 256)
#define OFF_BASE (OFF_AM + 256)
#define SM_TOTAL (OFF_BASE + 512)    // 36352

#define NEG_HALF_LOG2E (-0.7213475204444817f)
#define LOG2E          ( 1.4426950408889634f)

// ---------------- helpers ----------------
__device__ __forceinline__ uint32_t smem_u32(const void* p) {
    uint32_t a;
    asm("{ .reg .u64 t; cvta.to.shared.u64 t, %1; cvt.u32.u64 %0, t; }"
        : "=r"(a) : "l"(p));
    return a;
}
__device__ __forceinline__ float ex2f(float v) {
    float y; asm("ex2.approx.f32 %0, %1;" : "=f"(y) : "f"(v)); return y;
}
__device__ __forceinline__ float lg2f(float v) {
    float y; asm("lg2.approx.f32 %0, %1;" : "=f"(y) : "f"(v)); return y;
}
// truncate to bf16-representable value (1 LOP instead of 2 cvts; exact in bf16)
__device__ __forceinline__ float tbf(float v) {
    return __uint_as_float(__float_as_uint(v) & 0xffff0000u);
}
// one-instruction pack: lo -> bits 0-15, hi -> bits 16-31
__device__ __forceinline__ uint32_t pkbf(float lo, float hi) {
    uint32_t r;
    asm("cvt.rn.bf16x2.f32 %0, %1, %2;" : "=r"(r) : "f"(hi), "f"(lo));
    return r;
}
__device__ __forceinline__ void ldmx4(uint32_t addr, uint32_t& r0, uint32_t& r1,
                                      uint32_t& r2, uint32_t& r3) {
    asm volatile("ldmatrix.sync.aligned.m8n8.x4.shared.b16 {%0,%1,%2,%3}, [%4];"
                 : "=r"(r0), "=r"(r1), "=r"(r2), "=r"(r3) : "r"(addr));
}
__device__ __forceinline__ void ldmx2(uint32_t addr, uint32_t& r0, uint32_t& r1) {
    asm volatile("ldmatrix.sync.aligned.m8n8.x2.shared.b16 {%0,%1}, [%2];"
                 : "=r"(r0), "=r"(r1) : "r"(addr));
}
__device__ __forceinline__ void mma16816(float& d0, float& d1, float& d2, float& d3,
                                         uint32_t a0, uint32_t a1, uint32_t a2,
                                         uint32_t a3, uint32_t b0, uint32_t b1) {
    asm volatile("mma.sync.aligned.m16n8k16.row.col.f32.bf16.bf16.f32 "
                 "{%0,%1,%2,%3}, {%4,%5,%6,%7}, {%8,%9}, {%0,%1,%2,%3};"
                 : "+f"(d0), "+f"(d1), "+f"(d2), "+f"(d3)
                 : "r"(a0), "r"(a1), "r"(a2), "r"(a3), "r"(b0), "r"(b1));
}

// K layout (80): kt0-2 = T (dh|dm|dl x bits), kt3 = xh[16], kt4 = xl[16]
// base(row), lam(col), bias(col) applied exactly in the fp32 epilogue.
// Fallback = (sum_j am_j * ro_j) / max(sum am, 1) — accumulated in-loop.

__global__ __launch_bounds__(TPB, 6)
void anfis_mma(const float* __restrict__ x,
               const float* __restrict__ center,
               const float* __restrict__ log_sigma,
               const float* __restrict__ consequent,
               const int*   __restrict__ rule_idx,
               const float* __restrict__ amask,
               float* __restrict__ out, int B)
{
    extern __shared__ __align__(16) char dyn[];
    __shared__ float4 s_ci[N_IN];   // (c0, c1, inv0, inv1)

    const int tid  = threadIdx.x;
    const int lane = tid & 31;
    const int warp = tid >> 5;
    const uint32_t smA = smem_u32(dyn);

    // ---- stage 0: centers / inverse sigmas ---------------------------------
    if (tid < N_IN) {
        float c0 = center[tid * 2 + 0], c1 = center[tid * 2 + 1];
        float i0 = __fdividef(1.0f, ex2f(log_sigma[tid * 2 + 0] * LOG2E) + 1e-6f);
        float i1 = __fdividef(1.0f, ex2f(log_sigma[tid * 2 + 1] * LOG2E) + 1e-6f);
        s_ci[tid] = make_float4(c0, c1, i0, i1);
    }
    __syncthreads();

    // ---- stage 1: A row (per thread = one row) + base ----------------------
    const int gr = blockIdx.x * ROWS + tid;
    const int rs = (gr < B) ? gr : (B - 1);
    const float4* xv = reinterpret_cast<const float4*>(x + (size_t)rs * N_IN);
    float4 v0 = xv[0], v1 = xv[1], v2 = xv[2], v3 = xv[3];
    float xr[N_IN] = {v0.x, v0.y, v0.z, v0.w, v1.x, v1.y, v1.z, v1.w,
                      v2.x, v2.y, v2.z, v2.w, v3.x, v3.y, v3.z, v3.w};

    float base = 0.f;
    uint32_t wdh[8], wdm[8], wdl[8], wxh[8], wxl[8];
    #pragma unroll
    for (int i = 0; i < N_IN; i += 2) {
        float df[2], xh[2], xl[2];
        #pragma unroll
        for (int s = 0; s < 2; s++) {
            float4 ci = s_ci[i + s];
            float d0 = (xr[i + s] - ci.x) * ci.z;
            float d1 = (xr[i + s] - ci.y) * ci.w;
            float l0 = d0 * d0 * NEG_HALF_LOG2E;
            float l1 = d1 * d1 * NEG_HALF_LOG2E;
            base += l0;
            df[s] = l1 - l0;
            xh[s] = tbf(xr[i + s]);
            xl[s] = xr[i + s] - xh[s];
        }
        float h0 = tbf(df[0]), m0 = tbf(df[0] - h0);
        float h1 = tbf(df[1]), m1 = tbf(df[1] - h1);
        wdh[i / 2] = pkbf(h0, h1);
        wdm[i / 2] = pkbf(m0, m1);
        wdl[i / 2] = pkbf(df[0] - h0 - m0, df[1] - h1 - m1);
        wxh[i / 2] = pkbf(xh[0], xh[1]);
        wxl[i / 2] = pkbf(xl[0], xl[1]);
    }
    {
        uint4* arow = reinterpret_cast<uint4*>(dyn + OFF_A + tid * A_STR);
        arow[0] = make_uint4(wdh[0], wdh[1], wdh[2], wdh[3]);
        arow[1] = make_uint4(wdh[4], wdh[5], wdh[6], wdh[7]);
        arow[2] = make_uint4(wdm[0], wdm[1], wdm[2], wdm[3]);
        arow[3] = make_uint4(wdm[4], wdm[5], wdm[6], wdm[7]);
        arow[4] = make_uint4(wdl[0], wdl[1], wdl[2], wdl[3]);
        arow[5] = make_uint4(wdl[4], wdl[5], wdl[6], wdl[7]);
        arow[6] = make_uint4(wxh[0], wxh[1], wxh[2], wxh[3]);
        arow[7] = make_uint4(wxh[4], wxh[5], wxh[6], wxh[7]);
        arow[8] = make_uint4(wxl[0], wxl[1], wxl[2], wxl[3]);
        arow[9] = make_uint4(wxl[4], wxl[5], wxl[6], wxl[7]);
        reinterpret_cast<float*>(dyn + OFF_BASE)[tid] = base;
    }

    // ---- stage 2: B rows in-CTA (thread j = rule j or RO j-64) -------------
    if (tid < N_RULES) {
        const int4* rv = reinterpret_cast<const int4*>(rule_idx + tid * N_IN);
        int4 b0 = rv[0], b1 = rv[1], b2 = rv[2], b3 = rv[3];
        int bits[N_IN] = {b0.x, b0.y, b0.z, b0.w, b1.x, b1.y, b1.z, b1.w,
                          b2.x, b2.y, b2.z, b2.w, b3.x, b3.y, b3.z, b3.w};
        uint32_t wb[8];
        #pragma unroll
        for (int i = 0; i < N_IN; i += 2)
            wb[i / 2] = pkbf((float)bits[i], (float)bits[i + 1]);
        uint4* row = reinterpret_cast<uint4*>(dyn + OFF_BT + tid * BT_STR);
        uint4 lo = make_uint4(wb[0], wb[1], wb[2], wb[3]);
        uint4 hi = make_uint4(wb[4], wb[5], wb[6], wb[7]);
        row[0] = lo; row[1] = hi;
        row[2] = lo; row[3] = hi;
        row[4] = lo; row[5] = hi;
        row[6] = make_uint4(0, 0, 0, 0);
        float am = amask[tid];
        reinterpret_cast<float*>(dyn + OFF_LAM)[tid]  = lg2f(am); // am=0 -> -inf -> firing 0
        reinterpret_cast<float*>(dyn + OFF_BIAS)[tid] = consequent[tid * 17 + 16];
        reinterpret_cast<float*>(dyn + OFF_AM)[tid]   = am;
    } else {
        const int r = tid - N_RULES;
        const float* cr = consequent + r * 17;
        uint32_t wb[8];
        #pragma unroll
        for (int i = 0; i < N_IN; i += 2)
            wb[i / 2] = pkbf(cr[i], cr[i + 1]);
        uint4* row = reinterpret_cast<uint4*>(dyn + OFF_BR + r * BR_STR);
        uint4 lo = make_uint4(wb[0], wb[1], wb[2], wb[3]);
        uint4 hi = make_uint4(wb[4], wb[5], wb[6], wb[7]);
        row[0] = lo; row[1] = hi;   // xh slots
        row[2] = lo; row[3] = hi;   // xl slots (same Ch)
        row[4] = make_uint4(0, 0, 0, 0);
    }
    __syncthreads();

    // ---- stage 3: MMA + fp32 epilogue (fallback fused) ---------------------
    const int q = lane >> 2;
    const int t = lane & 3;
    const uint32_t smBT = smA + OFF_BT;
    const uint32_t smBR = smA + OFF_BR;
    const float* sBase  = reinterpret_cast<const float*>(dyn + OFF_BASE);
    const float2* lam2  = reinterpret_cast<const float2*>(dyn + OFF_LAM);
    const float2* bias2 = reinterpret_cast<const float2*>(dyn + OFF_BIAS);
    const float2* am2   = reinterpret_cast<const float2*>(dyn + OFF_AM);

    uint32_t af[2][5][4];
    float baseR[2][2];
    #pragma unroll
    for (int mt = 0; mt < 2; mt++) {
        int R = warp * 32 + mt * 16;
        int ar = R + (lane & 15);
        int ac0 = (lane >> 4) << 3;
        #pragma unroll
        for (int kt = 0; kt < 5; kt++)
            ldmx4(smA + ar * A_STR + (kt * 16 + ac0) * 2,
                  af[mt][kt][0], af[mt][kt][1], af[mt][kt][2], af[mt][kt][3]);
        baseR[mt][0] = sBase[R + q];
        baseR[mt][1] = sBase[R + q + 8];
    }

    float fs[2][2]  = {{0.f, 0.f}, {0.f, 0.f}};
    float acc[2][2] = {{0.f, 0.f}, {0.f, 0.f}};
    float fba[2][2] = {{0.f, 0.f}, {0.f, 0.f}};
    float dsum = 0.f;

    #pragma unroll
    for (int nt = 0; nt < 8; nt++) {
        int brj = nt * 8 + (lane & 7);
        int bc0 = lane & 8;
        uint32_t bt[3][2], br[2][2];
        #pragma unroll
        for (int k = 0; k < 3; k++)
            ldmx2(smBT + brj * BT_STR + (k * 16 + bc0) * 2, bt[k][0], bt[k][1]);
        #pragma unroll
        for (int k = 0; k < 2; k++)
            ldmx2(smBR + brj * BR_STR + (k * 16 + bc0) * 2, br[k][0], br[k][1]);

        float2 lm = lam2[nt * 4 + t];
        float2 bs = bias2[nt * 4 + t];
        float2 av = am2[nt * 4 + t];
        dsum += av.x + av.y;

        #pragma unroll
        for (int mt = 0; mt < 2; mt++) {
            float t0 = 0.f, t1 = 0.f, t2 = 0.f, t3 = 0.f;
            float r0 = 0.f, r1 = 0.f, r2 = 0.f, r3 = 0.f;
            #pragma unroll
            for (int k = 0; k < 3; k++)
                mma16816(t0, t1, t2, t3, af[mt][k][0], af[mt][k][1],
                         af[mt][k][2], af[mt][k][3], bt[k][0], bt[k][1]);
            #pragma unroll
            for (int k = 0; k < 2; k++)
                mma16816(r0, r1, r2, r3, af[mt][k + 3][0], af[mt][k + 3][1],
                         af[mt][k + 3][2], af[mt][k + 3][3], br[k][0], br[k][1]);

            float ro0 = r0 + bs.x, ro1 = r1 + bs.y;
            float ro2 = r2 + bs.x, ro3 = r3 + bs.y;
            float f0 = ex2f(t0 + baseR[mt][0] + lm.x);
            float f1 = ex2f(t1 + baseR[mt][0] + lm.y);
            float f2 = ex2f(t2 + baseR[mt][1] + lm.x);
            float f3 = ex2f(t3 + baseR[mt][1] + lm.y);
            fs[mt][0] += f0 + f1;
            acc[mt][0] = fmaf(f0, ro0, fmaf(f1, ro1, acc[mt][0]));
            fba[mt][0] = fmaf(av.x, ro0, fmaf(av.y, ro1, fba[mt][0]));
            fs[mt][1] += f2 + f3;
            acc[mt][1] = fmaf(f2, ro2, fmaf(f3, ro3, acc[mt][1]));
            fba[mt][1] = fmaf(av.x, ro2, fmaf(av.y, ro3, fba[mt][1]));
        }
    }

    #pragma unroll
    for (int d = 1; d <= 2; d <<= 1)
        dsum += __shfl_xor_sync(0xffffffffu, dsum, d);
    const float inv_den = __fdividef(1.0f, fmaxf(dsum, 1.0f));

    #pragma unroll
    for (int mt = 0; mt < 2; mt++) {
        float fsA = fs[mt][0], accA = acc[mt][0], fbA = fba[mt][0];
        float fsB = fs[mt][1], accB = acc[mt][1], fbB = fba[mt][1];
        #pragma unroll
        for (int d = 1; d <= 2; d <<= 1) {
            fsA  += __shfl_xor_sync(0xffffffffu, fsA,  d);
            accA += __shfl_xor_sync(0xffffffffu, accA, d);
            fbA  += __shfl_xor_sync(0xffffffffu, fbA,  d);
            fsB  += __shfl_xor_sync(0xffffffffu, fsB,  d);
            accB += __shfl_xor_sync(0xffffffffu, accB, d);
            fbB  += __shfl_xor_sync(0xffffffffu, fbB,  d);
        }
        if (t == 0) {
            int R = warp * 32 + mt * 16;
            int rA = R + q, rB = R + q + 8;
            float zA = (fsA <= 1e-12f) ? (fbA * inv_den) : __fdividef(accA, fsA);
            float zB = (fsB <= 1e-12f) ? (fbB * inv_den) : __fdividef(accB, fsB);
            float sA = __fdividef(1.0f, 1.0f + ex2f(-zA * LOG2E));
            float sB = __fdividef(1.0f, 1.0f + ex2f(-zB * LOG2E));
            sA = fminf(fmaxf(sA, 1e-7f), 1.0f - 1e-7f);
            sB = fminf(fmaxf(sB, 1e-7f), 1.0f - 1e-7f);
            int gA = blockIdx.x * ROWS + rA;
            int gB = blockIdx.x * ROWS + rB;
            if (gA < B) out[gA] = sA;
            if (gB < B) out[gB] = sB;
        }
    }
}

extern "C" void kernel_launch(void* const* d_in, const int* in_sizes, int n_in,
                              void* d_out, int out_size)
{
    const float* x          = (const float*)d_in[0];
    const float* center     = (const float*)d_in[1];
    const float* log_sigma  = (const float*)d_in[2];
    const float* consequent = (const float*)d_in[3];
    const int*   rule_idx   = (const int*)  d_in[4];
    const float* amask      = (const float*)d_in[5];
    float*       out        = (float*)d_out;

    int B = in_sizes[0] / N_IN;
    int grid = (B + ROWS - 1) / ROWS;

    cudaFuncSetAttribute(anfis_mma, cudaFuncAttributeMaxDynamicSharedMemorySize,
                         SM_TOTAL);
    anfis_mma<<<grid, TPB, SM_TOTAL>>>(x, center, log_sigma, consequent,
                                       rule_idx, amask, out, B);
}

// round 14
// speedup vs baseline: 1.1183x; 1.1183x over previous
#include <cuda_runtime.h>
#include <cuda_bf16.h>
#include <cstdint>

#define N_IN    16
#define N_RULES 64
#define TPB     128
#define ROWS    128

#define A_STR   176          // A row stride bytes (80 bf16 slots + pad)
#define BT_STR  112          // B-T row: 48 slots + pad
#define BR_STR  80           // B-RO row: 32 slots + pad

#define OFF_A    0
#define OFF_BT   22528       // 128*176
#define OFF_BR   (OFF_BT + 7168)
#define OFF_LAM  (OFF_BR + 5120)
#define OFF_BIAS (OFF_LAM + 256)
#define OFF_AM   (OFF_BIAS + 256)
#define OFF_BASE (OFF_AM + 256)
#define SM_TOTAL (OFF_BASE + 512)    // 36352

#define NEG_HALF_LOG2E (-0.7213475204444817f)
#define LOG2E          ( 1.4426950408889634f)

// ---------------- helpers ----------------
__device__ __forceinline__ uint32_t smem_u32(const void* p) {
    uint32_t a;
    asm("{ .reg .u64 t; cvta.to.shared.u64 t, %1; cvt.u32.u64 %0, t; }"
        : "=r"(a) : "l"(p));
    return a;
}
__device__ __forceinline__ float ex2f(float v) {
    float y; asm("ex2.approx.f32 %0, %1;" : "=f"(y) : "f"(v)); return y;
}
__device__ __forceinline__ float lg2f(float v) {
    float y; asm("lg2.approx.f32 %0, %1;" : "=f"(y) : "f"(v)); return y;
}
// truncate to bf16-representable value (1 LOP instead of 2 cvts; exact in bf16)
__device__ __forceinline__ float tbf(float v) {
    return __uint_as_float(__float_as_uint(v) & 0xffff0000u);
}
// one-instruction pack: lo -> bits 0-15, hi -> bits 16-31
__device__ __forceinline__ uint32_t pkbf(float lo, float hi) {
    uint32_t r;
    asm("cvt.rn.bf16x2.f32 %0, %1, %2;" : "=r"(r) : "f"(hi), "f"(lo));
    return r;
}
__device__ __forceinline__ void ldmx4(uint32_t addr, uint32_t& r0, uint32_t& r1,
                                      uint32_t& r2, uint32_t& r3) {
    asm volatile("ldmatrix.sync.aligned.m8n8.x4.shared.b16 {%0,%1,%2,%3}, [%4];"
                 : "=r"(r0), "=r"(r1), "=r"(r2), "=r"(r3) : "r"(addr));
}
__device__ __forceinline__ void ldmx2(uint32_t addr, uint32_t& r0, uint32_t& r1) {
    asm volatile("ldmatrix.sync.aligned.m8n8.x2.shared.b16 {%0,%1}, [%2];"
                 : "=r"(r0), "=r"(r1) : "r"(addr));
}
__device__ __forceinline__ void mma16816(float& d0, float& d1, float& d2, float& d3,
                                         uint32_t a0, uint32_t a1, uint32_t a2,
                                         uint32_t a3, uint32_t b0, uint32_t b1) {
    asm volatile("mma.sync.aligned.m16n8k16.row.col.f32.bf16.bf16.f32 "
                 "{%0,%1,%2,%3}, {%4,%5,%6,%7}, {%8,%9}, {%0,%1,%2,%3};"
                 : "+f"(d0), "+f"(d1), "+f"(d2), "+f"(d3)
                 : "r"(a0), "r"(a1), "r"(a2), "r"(a3), "r"(b0), "r"(b1));
}

// K layout (80): kt0-2 = T (dh|dm|dl x bits), kt3 = xh[16], kt4 = xl[16]
// base(row), lam(col), bias(col) applied exactly in the fp32 epilogue.
// Fallback = (sum_j am_j * ro_j) / max(sum am, 1) — accumulated in-loop.
// mt slabs processed SEQUENTIALLY to halve live A-fragment registers
// (fits occupancy 6 without spills; B frags reloaded per slab).

__global__ __launch_bounds__(TPB, 6)
void anfis_mma(const float* __restrict__ x,
               const float* __restrict__ center,
               const float* __restrict__ log_sigma,
               const float* __restrict__ consequent,
               const int*   __restrict__ rule_idx,
               const float* __restrict__ amask,
               float* __restrict__ out, int B)
{
    extern __shared__ __align__(16) char dyn[];
    __shared__ float4 s_ci[N_IN];   // (c0, c1, inv0, inv1)

    const int tid  = threadIdx.x;
    const int lane = tid & 31;
    const int warp = tid >> 5;
    const uint32_t smA = smem_u32(dyn);

    // ---- stage 0: centers / inverse sigmas ---------------------------------
    if (tid < N_IN) {
        float c0 = center[tid * 2 + 0], c1 = center[tid * 2 + 1];
        float i0 = __fdividef(1.0f, ex2f(log_sigma[tid * 2 + 0] * LOG2E) + 1e-6f);
        float i1 = __fdividef(1.0f, ex2f(log_sigma[tid * 2 + 1] * LOG2E) + 1e-6f);
        s_ci[tid] = make_float4(c0, c1, i0, i1);
    }
    __syncthreads();

    // ---- stage 1: A row (per thread = one row) + base ----------------------
    const int gr = blockIdx.x * ROWS + tid;
    const int rs = (gr < B) ? gr : (B - 1);
    const float4* xv = reinterpret_cast<const float4*>(x + (size_t)rs * N_IN);
    float4 v0 = xv[0], v1 = xv[1], v2 = xv[2], v3 = xv[3];
    float xr[N_IN] = {v0.x, v0.y, v0.z, v0.w, v1.x, v1.y, v1.z, v1.w,
                      v2.x, v2.y, v2.z, v2.w, v3.x, v3.y, v3.z, v3.w};

    float base = 0.f;
    uint32_t wdh[8], wdm[8], wdl[8], wxh[8], wxl[8];
    #pragma unroll
    for (int i = 0; i < N_IN; i += 2) {
        float df[2], xh[2], xl[2];
        #pragma unroll
        for (int s = 0; s < 2; s++) {
            float4 ci = s_ci[i + s];
            float d0 = (xr[i + s] - ci.x) * ci.z;
            float d1 = (xr[i + s] - ci.y) * ci.w;
            float l0 = d0 * d0 * NEG_HALF_LOG2E;
            float l1 = d1 * d1 * NEG_HALF_LOG2E;
            base += l0;
            df[s] = l1 - l0;
            xh[s] = tbf(xr[i + s]);
            xl[s] = xr[i + s] - xh[s];
        }
        float h0 = tbf(df[0]), m0 = tbf(df[0] - h0);
        float h1 = tbf(df[1]), m1 = tbf(df[1] - h1);
        wdh[i / 2] = pkbf(h0, h1);
        wdm[i / 2] = pkbf(m0, m1);
        wdl[i / 2] = pkbf(df[0] - h0 - m0, df[1] - h1 - m1);
        wxh[i / 2] = pkbf(xh[0], xh[1]);
        wxl[i / 2] = pkbf(xl[0], xl[1]);
    }
    {
        uint4* arow = reinterpret_cast<uint4*>(dyn + OFF_A + tid * A_STR);
        arow[0] = make_uint4(wdh[0], wdh[1], wdh[2], wdh[3]);
        arow[1] = make_uint4(wdh[4], wdh[5], wdh[6], wdh[7]);
        arow[2] = make_uint4(wdm[0], wdm[1], wdm[2], wdm[3]);
        arow[3] = make_uint4(wdm[4], wdm[5], wdm[6], wdm[7]);
        arow[4] = make_uint4(wdl[0], wdl[1], wdl[2], wdl[3]);
        arow[5] = make_uint4(wdl[4], wdl[5], wdl[6], wdl[7]);
        arow[6] = make_uint4(wxh[0], wxh[1], wxh[2], wxh[3]);
        arow[7] = make_uint4(wxh[4], wxh[5], wxh[6], wxh[7]);
        arow[8] = make_uint4(wxl[0], wxl[1], wxl[2], wxl[3]);
        arow[9] = make_uint4(wxl[4], wxl[5], wxl[6], wxl[7]);
        reinterpret_cast<float*>(dyn + OFF_BASE)[tid] = base;
    }

    // ---- stage 2: B rows in-CTA (thread j = rule j or RO j-64) -------------
    if (tid < N_RULES) {
        const int4* rv = reinterpret_cast<const int4*>(rule_idx + tid * N_IN);
        int4 b0 = rv[0], b1 = rv[1], b2 = rv[2], b3 = rv[3];
        int bits[N_IN] = {b0.x, b0.y, b0.z, b0.w, b1.x, b1.y, b1.z, b1.w,
                          b2.x, b2.y, b2.z, b2.w, b3.x, b3.y, b3.z, b3.w};
        uint32_t wb[8];
        #pragma unroll
        for (int i = 0; i < N_IN; i += 2)
            wb[i / 2] = pkbf((float)bits[i], (float)bits[i + 1]);
        uint4* row = reinterpret_cast<uint4*>(dyn + OFF_BT + tid * BT_STR);
        uint4 lo = make_uint4(wb[0], wb[1], wb[2], wb[3]);
        uint4 hi = make_uint4(wb[4], wb[5], wb[6], wb[7]);
        row[0] = lo; row[1] = hi;
        row[2] = lo; row[3] = hi;
        row[4] = lo; row[5] = hi;
        row[6] = make_uint4(0, 0, 0, 0);
        float am = amask[tid];
        reinterpret_cast<float*>(dyn + OFF_LAM)[tid]  = lg2f(am); // am=0 -> -inf -> firing 0
        reinterpret_cast<float*>(dyn + OFF_BIAS)[tid] = consequent[tid * 17 + 16];
        reinterpret_cast<float*>(dyn + OFF_AM)[tid]   = am;
    } else {
        const int r = tid - N_RULES;
        const float* cr = consequent + r * 17;
        uint32_t wb[8];
        #pragma unroll
        for (int i = 0; i < N_IN; i += 2)
            wb[i / 2] = pkbf(cr[i], cr[i + 1]);
        uint4* row = reinterpret_cast<uint4*>(dyn + OFF_BR + r * BR_STR);
        uint4 lo = make_uint4(wb[0], wb[1], wb[2], wb[3]);
        uint4 hi = make_uint4(wb[4], wb[5], wb[6], wb[7]);
        row[0] = lo; row[1] = hi;   // xh slots
        row[2] = lo; row[3] = hi;   // xl slots (same Ch)
        row[4] = make_uint4(0, 0, 0, 0);
    }
    __syncthreads();

    // ---- stage 3: MMA + fp32 epilogue, one 16-row slab at a time -----------
    const int q = lane >> 2;
    const int t = lane & 3;
    const uint32_t smBT = smA + OFF_BT;
    const uint32_t smBR = smA + OFF_BR;
    const float* sBase  = reinterpret_cast<const float*>(dyn + OFF_BASE);
    const float2* lam2  = reinterpret_cast<const float2*>(dyn + OFF_LAM);
    const float2* bias2 = reinterpret_cast<const float2*>(dyn + OFF_BIAS);
    const float2* am2   = reinterpret_cast<const float2*>(dyn + OFF_AM);

    float inv_den = 0.f;

    #pragma unroll
    for (int mt = 0; mt < 2; mt++) {
        const int R = warp * 32 + mt * 16;

        // A fragments for THIS slab only (20 regs live)
        uint32_t af[5][4];
        {
            int ar = R + (lane & 15);
            int ac0 = (lane >> 4) << 3;
            #pragma unroll
            for (int kt = 0; kt < 5; kt++)
                ldmx4(smA + ar * A_STR + (kt * 16 + ac0) * 2,
                      af[kt][0], af[kt][1], af[kt][2], af[kt][3]);
        }
        const float baseA = sBase[R + q];
        const float baseB = sBase[R + q + 8];

        float fsA = 0.f, accA = 0.f, fbaA = 0.f;
        float fsB = 0.f, accB = 0.f, fbaB = 0.f;
        float dsum = 0.f;

        #pragma unroll
        for (int nt = 0; nt < 8; nt++) {
            int brj = nt * 8 + (lane & 7);
            int bc0 = lane & 8;
            uint32_t bt[3][2], br[2][2];
            #pragma unroll
            for (int k = 0; k < 3; k++)
                ldmx2(smBT + brj * BT_STR + (k * 16 + bc0) * 2, bt[k][0], bt[k][1]);
            #pragma unroll
            for (int k = 0; k < 2; k++)
                ldmx2(smBR + brj * BR_STR + (k * 16 + bc0) * 2, br[k][0], br[k][1]);

            float2 lm = lam2[nt * 4 + t];
            float2 bs = bias2[nt * 4 + t];
            float2 av = am2[nt * 4 + t];
            dsum += av.x + av.y;

            float t0 = 0.f, t1 = 0.f, t2 = 0.f, t3 = 0.f;
            float r0 = 0.f, r1 = 0.f, r2 = 0.f, r3 = 0.f;
            #pragma unroll
            for (int k = 0; k < 3; k++)
                mma16816(t0, t1, t2, t3, af[k][0], af[k][1],
                         af[k][2], af[k][3], bt[k][0], bt[k][1]);
            #pragma unroll
            for (int k = 0; k < 2; k++)
                mma16816(r0, r1, r2, r3, af[k + 3][0], af[k + 3][1],
                         af[k + 3][2], af[k + 3][3], br[k][0], br[k][1]);

            float ro0 = r0 + bs.x, ro1 = r1 + bs.y;
            float ro2 = r2 + bs.x, ro3 = r3 + bs.y;
            float f0 = ex2f(t0 + baseA + lm.x);
            float f1 = ex2f(t1 + baseA + lm.y);
            float f2 = ex2f(t2 + baseB + lm.x);
            float f3 = ex2f(t3 + baseB + lm.y);
            fsA += f0 + f1;
            accA = fmaf(f0, ro0, fmaf(f1, ro1, accA));
            fbaA = fmaf(av.x, ro0, fmaf(av.y, ro1, fbaA));
            fsB += f2 + f3;
            accB = fmaf(f2, ro2, fmaf(f3, ro3, accB));
            fbaB = fmaf(av.x, ro2, fmaf(av.y, ro3, fbaB));
        }

        if (mt == 0) {
            #pragma unroll
            for (int d = 1; d <= 2; d <<= 1)
                dsum += __shfl_xor_sync(0xffffffffu, dsum, d);
            inv_den = __fdividef(1.0f, fmaxf(dsum, 1.0f));
        }

        #pragma unroll
        for (int d = 1; d <= 2; d <<= 1) {
            fsA  += __shfl_xor_sync(0xffffffffu, fsA,  d);
            accA += __shfl_xor_sync(0xffffffffu, accA, d);
            fbaA += __shfl_xor_sync(0xffffffffu, fbaA, d);
            fsB  += __shfl_xor_sync(0xffffffffu, fsB,  d);
            accB += __shfl_xor_sync(0xffffffffu, accB, d);
            fbaB += __shfl_xor_sync(0xffffffffu, fbaB, d);
        }
        if (t == 0) {
            int rA = R + q, rB = R + q + 8;
            float zA = (fsA <= 1e-12f) ? (fbaA * inv_den) : __fdividef(accA, fsA);
            float zB = (fsB <= 1e-12f) ? (fbaB * inv_den) : __fdividef(accB, fsB);
            float sA = __fdividef(1.0f, 1.0f + ex2f(-zA * LOG2E));
            float sB = __fdividef(1.0f, 1.0f + ex2f(-zB * LOG2E));
            sA = fminf(fmaxf(sA, 1e-7f), 1.0f - 1e-7f);
            sB = fminf(fmaxf(sB, 1e-7f), 1.0f - 1e-7f);
            int gA = blockIdx.x * ROWS + rA;
            int gB = blockIdx.x * ROWS + rB;
            if (gA < B) out[gA] = sA;
            if (gB < B) out[gB] = sB;
        }
    }
}

extern "C" void kernel_launch(void* const* d_in, const int* in_sizes, int n_in,
                              void* d_out, int out_size)
{
    const float* x          = (const float*)d_in[0];
    const float* center     = (const float*)d_in[1];
    const float* log_sigma  = (const float*)d_in[2];
    const float* consequent = (const float*)d_in[3];
    const int*   rule_idx   = (const int*)  d_in[4];
    const float* amask      = (const float*)d_in[5];
    float*       out        = (float*)d_out;

    int B = in_sizes[0] / N_IN;
    int grid = (B + ROWS - 1) / ROWS;

    cudaFuncSetAttribute(anfis_mma, cudaFuncAttributeMaxDynamicSharedMemorySize,
                         SM_TOTAL);
    anfis_mma<<<grid, TPB, SM_TOTAL>>>(x, center, log_sigma, consequent,
                                       rule_idx, amask, out, B);
}

// round 15
// speedup vs baseline: 1.2234x; 1.0939x over previous
#include <cuda_runtime.h>
#include <cuda_fp16.h>
#include <cstdint>

#define N_IN    16
#define N_RULES 64
#define TPB     128
#define ROWS    128

#define A_STR   144          // A row stride bytes (64 fp16 slots + 16 pad)
#define BT_STR  80           // B-T row: 32 slots + 16 pad
#define BR_STR  80           // B-RO row: 32 slots + 16 pad

#define OFF_A    0
#define OFF_BT   18432       // 128*144
#define OFF_BR   (OFF_BT + 5120)
#define OFF_LB   (OFF_BR + 5120)   // float4[32]: (lam_e, lam_o, bias_e, bias_o)
#define OFF_AM   (OFF_LB + 512)    // float[64]
#define OFF_BASE (OFF_AM + 256)    // float[128]
#define SM_TOTAL (OFF_BASE + 512)  // 29952

#define NEG_HALF_LOG2E (-0.7213475204444817f)
#define SQRT_HL2E      ( 0.8493217806f)      // sqrt(0.72134752)
#define LOG2E          ( 1.4426950408889634f)

// ---------------- helpers ----------------
__device__ __forceinline__ uint32_t smem_u32(const void* p) {
    uint32_t a;
    asm("{ .reg .u64 t; cvta.to.shared.u64 t, %1; cvt.u32.u64 %0, t; }"
        : "=r"(a) : "l"(p));
    return a;
}
__device__ __forceinline__ float ex2f(float v) {
    float y; asm("ex2.approx.f32 %0, %1;" : "=f"(y) : "f"(v)); return y;
}
__device__ __forceinline__ float lg2f(float v) {
    float y; asm("lg2.approx.f32 %0, %1;" : "=f"(y) : "f"(v)); return y;
}
// truncate to fp16-representable value (keep 10 mantissa bits; 1 LOP)
__device__ __forceinline__ float tf16(float v) {
    return __uint_as_float(__float_as_uint(v) & 0xffffe000u);
}
// one-instruction pack to fp16x2: lo -> bits 0-15, hi -> bits 16-31
__device__ __forceinline__ uint32_t pkhf(float lo, float hi) {
    uint32_t r;
    asm("cvt.rn.f16x2.f32 %0, %1, %2;" : "=r"(r) : "f"(hi), "f"(lo));
    return r;
}
__device__ __forceinline__ void ldmx4(uint32_t addr, uint32_t& r0, uint32_t& r1,
                                      uint32_t& r2, uint32_t& r3) {
    asm volatile("ldmatrix.sync.aligned.m8n8.x4.shared.b16 {%0,%1,%2,%3}, [%4];"
                 : "=r"(r0), "=r"(r1), "=r"(r2), "=r"(r3) : "r"(addr));
}
__device__ __forceinline__ void ldmx2(uint32_t addr, uint32_t& r0, uint32_t& r1) {
    asm volatile("ldmatrix.sync.aligned.m8n8.x2.shared.b16 {%0,%1}, [%2];"
                 : "=r"(r0), "=r"(r1) : "r"(addr));
}
__device__ __forceinline__ void mma16816(float& d0, float& d1, float& d2, float& d3,
                                         uint32_t a0, uint32_t a1, uint32_t a2,
                                         uint32_t a3, uint32_t b0, uint32_t b1) {
    asm volatile("mma.sync.aligned.m16n8k16.row.col.f32.f16.f16.f32 "
                 "{%0,%1,%2,%3}, {%4,%5,%6,%7}, {%8,%9}, {%0,%1,%2,%3};"
                 : "+f"(d0), "+f"(d1), "+f"(d2), "+f"(d3)
                 : "r"(a0), "r"(a1), "r"(a2), "r"(a3), "r"(b0), "r"(b1));
}

// K layout (64, fp16): kt0 = th (df hi), kt1 = tl (df residual),
//                      kt2 = xh, kt3 = xl.
// fp16 2-split residual = df*2^-21 == bf16 3-split residual (same T error).
// base(row), lam(col), bias(col) applied exactly in the fp32 epilogue.
// Fallback = (sum_j am_j * ro_j) / max(sum am, 1) — accumulated in-loop.
// mt slabs processed sequentially (16 live A-frag regs; no spills at occ 6).

__global__ __launch_bounds__(TPB, 6)
void anfis_mma(const float* __restrict__ x,
               const float* __restrict__ center,
               const float* __restrict__ log_sigma,
               const float* __restrict__ consequent,
               const int*   __restrict__ rule_idx,
               const float* __restrict__ amask,
               float* __restrict__ out, int B)
{
    extern __shared__ __align__(16) char dyn[];
    __shared__ float4 s_ci[N_IN];   // (nci0', i0', nci1', i1') pre-scaled

    const int tid  = threadIdx.x;
    const int lane = tid & 31;
    const int warp = tid >> 5;
    const uint32_t smA = smem_u32(dyn);

    // ---- stage 0: pre-scaled centers / inverse sigmas ----------------------
    if (tid < N_IN) {
        float c0 = center[tid * 2 + 0], c1 = center[tid * 2 + 1];
        float i0 = __fdividef(SQRT_HL2E, ex2f(log_sigma[tid * 2 + 0] * LOG2E) + 1e-6f);
        float i1 = __fdividef(SQRT_HL2E, ex2f(log_sigma[tid * 2 + 1] * LOG2E) + 1e-6f);
        s_ci[tid] = make_float4(-c0 * i0, i0, -c1 * i1, i1);
    }
    __syncthreads();

    // ---- stage 1: A row (per thread = one row) + base ----------------------
    const int gr = blockIdx.x * ROWS + tid;
    const int rs = (gr < B) ? gr : (B - 1);
    const float4* xv = reinterpret_cast<const float4*>(x + (size_t)rs * N_IN);
    float4 v0 = xv[0], v1 = xv[1], v2 = xv[2], v3 = xv[3];
    float xr[N_IN] = {v0.x, v0.y, v0.z, v0.w, v1.x, v1.y, v1.z, v1.w,
                      v2.x, v2.y, v2.z, v2.w, v3.x, v3.y, v3.z, v3.w};

    float base = 0.f;
    uint32_t wth[8], wtl[8], wxh[8], wxl[8];
    #pragma unroll
    for (int i = 0; i < N_IN; i += 2) {
        float df[2], xh[2], xl[2];
        #pragma unroll
        for (int s = 0; s < 2; s++) {
            float4 ci = s_ci[i + s];
            float d0 = fmaf(xr[i + s], ci.y, ci.x);    // (x-c0)*i0'
            float d1 = fmaf(xr[i + s], ci.w, ci.z);    // (x-c1)*i1'
            float l0 = -d0 * d0;                       // log2 mu0 (scaled in)
            float l1 = -d1 * d1;
            base += l0;
            df[s] = l1 - l0;
            xh[s] = tf16(xr[i + s]);
            xl[s] = xr[i + s] - xh[s];
        }
        float h0 = tf16(df[0]);
        float h1 = tf16(df[1]);
        wth[i / 2] = pkhf(h0, h1);
        wtl[i / 2] = pkhf(df[0] - h0, df[1] - h1);
        wxh[i / 2] = pkhf(xh[0], xh[1]);
        wxl[i / 2] = pkhf(xl[0], xl[1]);
    }
    {
        uint4* arow = reinterpret_cast<uint4*>(dyn + OFF_A + tid * A_STR);
        arow[0] = make_uint4(wth[0], wth[1], wth[2], wth[3]);
        arow[1] = make_uint4(wth[4], wth[5], wth[6], wth[7]);
        arow[2] = make_uint4(wtl[0], wtl[1], wtl[2], wtl[3]);
        arow[3] = make_uint4(wtl[4], wtl[5], wtl[6], wtl[7]);
        arow[4] = make_uint4(wxh[0], wxh[1], wxh[2], wxh[3]);
        arow[5] = make_uint4(wxh[4], wxh[5], wxh[6], wxh[7]);
        arow[6] = make_uint4(wxl[0], wxl[1], wxl[2], wxl[3]);
        arow[7] = make_uint4(wxl[4], wxl[5], wxl[6], wxl[7]);
        reinterpret_cast<float*>(dyn + OFF_BASE)[tid] = base;
    }

    // ---- stage 2: B rows in-CTA (thread j = rule j or RO j-64) -------------
    if (tid < N_RULES) {
        const int4* rv = reinterpret_cast<const int4*>(rule_idx + tid * N_IN);
        int4 b0 = rv[0], b1 = rv[1], b2 = rv[2], b3 = rv[3];
        int bits[N_IN] = {b0.x, b0.y, b0.z, b0.w, b1.x, b1.y, b1.z, b1.w,
                          b2.x, b2.y, b2.z, b2.w, b3.x, b3.y, b3.z, b3.w};
        uint32_t wb[8];
        #pragma unroll
        for (int i = 0; i < N_IN; i += 2)
            wb[i / 2] = pkhf((float)bits[i], (float)bits[i + 1]);
        uint4* row = reinterpret_cast<uint4*>(dyn + OFF_BT + tid * BT_STR);
        uint4 lo = make_uint4(wb[0], wb[1], wb[2], wb[3]);
        uint4 hi = make_uint4(wb[4], wb[5], wb[6], wb[7]);
        row[0] = lo; row[1] = hi;      // kt0 bits
        row[2] = lo; row[3] = hi;      // kt1 bits (same)
        float am = amask[tid];
        float* lb = reinterpret_cast<float*>(dyn + OFF_LB);
        lb[(tid >> 1) * 4 + (tid & 1)]     = lg2f(am);  // am=0 -> -inf -> f=0
        lb[(tid >> 1) * 4 + 2 + (tid & 1)] = consequent[tid * 17 + 16];
        reinterpret_cast<float*>(dyn + OFF_AM)[tid] = am;
    } else {
        const int r = tid - N_RULES;
        const float* cr = consequent + r * 17;
        uint32_t wb[8];
        #pragma unroll
        for (int i = 0; i < N_IN; i += 2)
            wb[i / 2] = pkhf(cr[i], cr[i + 1]);
        uint4* row = reinterpret_cast<uint4*>(dyn + OFF_BR + r * BR_STR);
        uint4 lo = make_uint4(wb[0], wb[1], wb[2], wb[3]);
        uint4 hi = make_uint4(wb[4], wb[5], wb[6], wb[7]);
        row[0] = lo; row[1] = hi;      // xh slots
        row[2] = lo; row[3] = hi;      // xl slots (same C)
    }
    __syncthreads();

    // ---- stage 3: MMA + fp32 epilogue, one 16-row slab at a time -----------
    const int q = lane >> 2;
    const int t = lane & 3;
    const uint32_t smBT = smA + OFF_BT;
    const uint32_t smBR = smA + OFF_BR;
    const float* sBase  = reinterpret_cast<const float*>(dyn + OFF_BASE);
    const float4* lb4   = reinterpret_cast<const float4*>(dyn + OFF_LB);
    const float2* am2   = reinterpret_cast<const float2*>(dyn + OFF_AM);

    float inv_den = 0.f;

    #pragma unroll
    for (int mt = 0; mt < 2; mt++) {
        const int R = warp * 32 + mt * 16;

        // A fragments for THIS slab only (16 regs live)
        uint32_t af[4][4];
        {
            int ar = R + (lane & 15);
            int ac0 = (lane >> 4) << 3;
            #pragma unroll
            for (int kt = 0; kt < 4; kt++)
                ldmx4(smA + ar * A_STR + (kt * 16 + ac0) * 2,
                      af[kt][0], af[kt][1], af[kt][2], af[kt][3]);
        }
        const float baseA = sBase[R + q];
        const float baseB = sBase[R + q + 8];

        float fsA = 0.f, accA = 0.f, fbaA = 0.f;
        float fsB = 0.f, accB = 0.f, fbaB = 0.f;
        float dsum = 0.f;

        #pragma unroll
        for (int nt = 0; nt < 8; nt++) {
            int brj = nt * 8 + (lane & 7);
            int bc0 = lane & 8;
            uint32_t bt[2][2], br[2][2];
            #pragma unroll
            for (int k = 0; k < 2; k++)
                ldmx2(smBT + brj * BT_STR + (k * 16 + bc0) * 2, bt[k][0], bt[k][1]);
            #pragma unroll
            for (int k = 0; k < 2; k++)
                ldmx2(smBR + brj * BR_STR + (k * 16 + bc0) * 2, br[k][0], br[k][1]);

            float4 lb = lb4[nt * 4 + t];        // (lam_e, lam_o, bias_e, bias_o)
            float2 av = am2[nt * 4 + t];
            dsum += av.x + av.y;

            float t0 = 0.f, t1 = 0.f, t2 = 0.f, t3 = 0.f;
            float r0 = 0.f, r1 = 0.f, r2 = 0.f, r3 = 0.f;
            #pragma unroll
            for (int k = 0; k < 2; k++)
                mma16816(t0, t1, t2, t3, af[k][0], af[k][1],
                         af[k][2], af[k][3], bt[k][0], bt[k][1]);
            #pragma unroll
            for (int k = 0; k < 2; k++)
                mma16816(r0, r1, r2, r3, af[k + 2][0], af[k + 2][1],
                         af[k + 2][2], af[k + 2][3], br[k][0], br[k][1]);

            float ro0 = r0 + lb.z, ro1 = r1 + lb.w;
            float ro2 = r2 + lb.z, ro3 = r3 + lb.w;
            float f0 = ex2f(t0 + baseA + lb.x);
            float f1 = ex2f(t1 + baseA + lb.y);
            float f2 = ex2f(t2 + baseB + lb.x);
            float f3 = ex2f(t3 + baseB + lb.y);
            fsA += f0 + f1;
            accA = fmaf(f0, ro0, fmaf(f1, ro1, accA));
            fbaA = fmaf(av.x, ro0, fmaf(av.y, ro1, fbaA));
            fsB += f2 + f3;
            accB = fmaf(f2, ro2, fmaf(f3, ro3, accB));
            fbaB = fmaf(av.x, ro2, fmaf(av.y, ro3, fbaB));
        }

        if (mt == 0) {
            #pragma unroll
            for (int d = 1; d <= 2; d <<= 1)
                dsum += __shfl_xor_sync(0xffffffffu, dsum, d);
            inv_den = __fdividef(1.0f, fmaxf(dsum, 1.0f));
        }

        #pragma unroll
        for (int d = 1; d <= 2; d <<= 1) {
            fsA  += __shfl_xor_sync(0xffffffffu, fsA,  d);
            accA += __shfl_xor_sync(0xffffffffu, accA, d);
            fbaA += __shfl_xor_sync(0xffffffffu, fbaA, d);
            fsB  += __shfl_xor_sync(0xffffffffu, fsB,  d);
            accB += __shfl_xor_sync(0xffffffffu, accB, d);
            fbaB += __shfl_xor_sync(0xffffffffu, fbaB, d);
        }
        if (t == 0) {
            int rA = R + q, rB = R + q + 8;
            float zA = (fsA <= 1e-12f) ? (fbaA * inv_den) : __fdividef(accA, fsA);
            float zB = (fsB <= 1e-12f) ? (fbaB * inv_den) : __fdividef(accB, fsB);
            float sA = __fdividef(1.0f, 1.0f + ex2f(-zA * LOG2E));
            float sB = __fdividef(1.0f, 1.0f + ex2f(-zB * LOG2E));
            sA = fminf(fmaxf(sA, 1e-7f), 1.0f - 1e-7f);
            sB = fminf(fmaxf(sB, 1e-7f), 1.0f - 1e-7f);
            int gA = blockIdx.x * ROWS + rA;
            int gB = blockIdx.x * ROWS + rB;
            if (gA < B) out[gA] = sA;
            if (gB < B) out[gB] = sB;
        }
    }
}

extern "C" void kernel_launch(void* const* d_in, const int* in_sizes, int n_in,
                              void* d_out, int out_size)
{
    const float* x          = (const float*)d_in[0];
    const float* center     = (const float*)d_in[1];
    const float* log_sigma  = (const float*)d_in[2];
    const float* consequent = (const float*)d_in[3];
    const int*   rule_idx   = (const int*)  d_in[4];
    const float* amask      = (const float*)d_in[5];
    float*       out        = (float*)d_out;

    int B = in_sizes[0] / N_IN;
    int grid = (B + ROWS - 1) / ROWS;

    anfis_mma<<<grid, TPB, SM_TOTAL>>>(x, center, log_sigma, consequent,
                                       rule_idx, amask, out, B);
}

// round 16
// speedup vs baseline: 1.2823x; 1.0481x over previous
#include <cuda_runtime.h>
#include <cuda_fp16.h>
#include <cstdint>

#define N_IN    16
#define N_RULES 64
#define TPB     128
#define ROWS    128

#define A_STR   112          // A row stride bytes (48 fp16 slots + 16 pad)
#define BT_STR  80           // B-T row: 32 slots + 16 pad
#define BR_STR  48           // B-RO row: 16 slots + 16 pad

#define OFF_A    0
#define OFF_BT   14336       // 128*112
#define OFF_BR   (OFF_BT + 5120)
#define OFF_LB   (OFF_BR + 3072)   // float4[32]: (lam_e, lam_o, bias_e, bias_o)
#define OFF_AM   (OFF_LB + 512)    // float[64]
#define OFF_BASE (OFF_AM + 256)    // float[128]
#define SM_TOTAL (OFF_BASE + 512)  // 26368

#define SQRT_HL2E ( 0.8493217806f)      // sqrt(0.5*log2(e))
#define LOG2E     ( 1.4426950408889634f)

// ---------------- helpers ----------------
__device__ __forceinline__ uint32_t smem_u32(const void* p) {
    uint32_t a;
    asm("{ .reg .u64 t; cvta.to.shared.u64 t, %1; cvt.u32.u64 %0, t; }"
        : "=r"(a) : "l"(p));
    return a;
}
__device__ __forceinline__ float ex2f(float v) {
    float y; asm("ex2.approx.f32 %0, %1;" : "=f"(y) : "f"(v)); return y;
}
__device__ __forceinline__ float lg2f(float v) {
    float y; asm("lg2.approx.f32 %0, %1;" : "=f"(y) : "f"(v)); return y;
}
// truncate to fp16-representable value (keep 10 mantissa bits; 1 LOP)
__device__ __forceinline__ float tf16(float v) {
    return __uint_as_float(__float_as_uint(v) & 0xffffe000u);
}
// one-instruction pack to fp16x2: lo -> bits 0-15, hi -> bits 16-31
__device__ __forceinline__ uint32_t pkhf(float lo, float hi) {
    uint32_t r;
    asm("cvt.rn.f16x2.f32 %0, %1, %2;" : "=r"(r) : "f"(hi), "f"(lo));
    return r;
}
__device__ __forceinline__ void ldmx4(uint32_t addr, uint32_t& r0, uint32_t& r1,
                                      uint32_t& r2, uint32_t& r3) {
    asm volatile("ldmatrix.sync.aligned.m8n8.x4.shared.b16 {%0,%1,%2,%3}, [%4];"
                 : "=r"(r0), "=r"(r1), "=r"(r2), "=r"(r3) : "r"(addr));
}
__device__ __forceinline__ void ldmx2(uint32_t addr, uint32_t& r0, uint32_t& r1) {
    asm volatile("ldmatrix.sync.aligned.m8n8.x2.shared.b16 {%0,%1}, [%2];"
                 : "=r"(r0), "=r"(r1) : "r"(addr));
}
__device__ __forceinline__ void mma16816(float& d0, float& d1, float& d2, float& d3,
                                         uint32_t a0, uint32_t a1, uint32_t a2,
                                         uint32_t a3, uint32_t b0, uint32_t b1) {
    asm volatile("mma.sync.aligned.m16n8k16.row.col.f32.f16.f16.f32 "
                 "{%0,%1,%2,%3}, {%4,%5,%6,%7}, {%8,%9}, {%0,%1,%2,%3};"
                 : "+f"(d0), "+f"(d1), "+f"(d2), "+f"(d3)
                 : "r"(a0), "r"(a1), "r"(a2), "r"(a3), "r"(b0), "r"(b1));
}

// K layout (48, fp16): kt0 = th (df hi), kt1 = tl (df residual), kt2 = xh.
// T keeps the 2-split (residual df*2^-21) to protect the fs<=1e-12 branch;
// RO uses rounded-fp16 x only (out err ~1e-5 rel; threshold 1e-3).
// base(row), lam(col), bias(col) applied exactly in the fp32 epilogue.
// Fallback = (sum_j am_j * ro_j) / max(sum am, 1) — accumulated in-loop.

__global__ __launch_bounds__(TPB, 6)
void anfis_mma(const float* __restrict__ x,
               const float* __restrict__ center,
               const float* __restrict__ log_sigma,
               const float* __restrict__ consequent,
               const int*   __restrict__ rule_idx,
               const float* __restrict__ amask,
               float* __restrict__ out, int B)
{
    extern __shared__ __align__(16) char dyn[];
    __shared__ float4 s_ci[N_IN];   // (-c0*i0', i0', -c1*i1', i1') pre-scaled

    const int tid  = threadIdx.x;
    const int lane = tid & 31;
    const int warp = tid >> 5;
    const uint32_t smA = smem_u32(dyn);

    // ---- stage 0: pre-scaled centers / inverse sigmas ----------------------
    if (tid < N_IN) {
        float c0 = center[tid * 2 + 0], c1 = center[tid * 2 + 1];
        float i0 = __fdividef(SQRT_HL2E, ex2f(log_sigma[tid * 2 + 0] * LOG2E) + 1e-6f);
        float i1 = __fdividef(SQRT_HL2E, ex2f(log_sigma[tid * 2 + 1] * LOG2E) + 1e-6f);
        s_ci[tid] = make_float4(-c0 * i0, i0, -c1 * i1, i1);
    }
    __syncthreads();

    // ---- stage 1: A row (per thread = one row) + base ----------------------
    const int gr = blockIdx.x * ROWS + tid;
    const int rs = (gr < B) ? gr : (B - 1);
    const float4* xv = reinterpret_cast<const float4*>(x + (size_t)rs * N_IN);
    float4 v0 = xv[0], v1 = xv[1], v2 = xv[2], v3 = xv[3];
    float xr[N_IN] = {v0.x, v0.y, v0.z, v0.w, v1.x, v1.y, v1.z, v1.w,
                      v2.x, v2.y, v2.z, v2.w, v3.x, v3.y, v3.z, v3.w};

    float base = 0.f;
    uint32_t wth[8], wtl[8], wxh[8];
    #pragma unroll
    for (int i = 0; i < N_IN; i += 2) {
        float df[2];
        #pragma unroll
        for (int s = 0; s < 2; s++) {
            float4 ci = s_ci[i + s];
            float d0 = fmaf(xr[i + s], ci.y, ci.x);    // (x-c0)*i0'
            float d1 = fmaf(xr[i + s], ci.w, ci.z);    // (x-c1)*i1'
            float l0 = -d0 * d0;                       // log2 mu0 (scale folded)
            float l1 = -d1 * d1;
            base += l0;
            df[s] = l1 - l0;
        }
        float h0 = tf16(df[0]);
        float h1 = tf16(df[1]);
        wth[i / 2] = pkhf(h0, h1);
        wtl[i / 2] = pkhf(df[0] - h0, df[1] - h1);
        wxh[i / 2] = pkhf(xr[i], xr[i + 1]);           // rounded fp16 x
    }
    {
        uint4* arow = reinterpret_cast<uint4*>(dyn + OFF_A + tid * A_STR);
        arow[0] = make_uint4(wth[0], wth[1], wth[2], wth[3]);
        arow[1] = make_uint4(wth[4], wth[5], wth[6], wth[7]);
        arow[2] = make_uint4(wtl[0], wtl[1], wtl[2], wtl[3]);
        arow[3] = make_uint4(wtl[4], wtl[5], wtl[6], wtl[7]);
        arow[4] = make_uint4(wxh[0], wxh[1], wxh[2], wxh[3]);
        arow[5] = make_uint4(wxh[4], wxh[5], wxh[6], wxh[7]);
        reinterpret_cast<float*>(dyn + OFF_BASE)[tid] = base;
    }

    // ---- stage 2: B rows in-CTA (thread j = rule j or RO j-64) -------------
    if (tid < N_RULES) {
        const int4* rv = reinterpret_cast<const int4*>(rule_idx + tid * N_IN);
        int4 b0 = rv[0], b1 = rv[1], b2 = rv[2], b3 = rv[3];
        int bits[N_IN] = {b0.x, b0.y, b0.z, b0.w, b1.x, b1.y, b1.z, b1.w,
                          b2.x, b2.y, b2.z, b2.w, b3.x, b3.y, b3.z, b3.w};
        uint32_t wb[8];
        #pragma unroll
        for (int i = 0; i < N_IN; i += 2)
            wb[i / 2] = pkhf((float)bits[i], (float)bits[i + 1]);
        uint4* row = reinterpret_cast<uint4*>(dyn + OFF_BT + tid * BT_STR);
        uint4 lo = make_uint4(wb[0], wb[1], wb[2], wb[3]);
        uint4 hi = make_uint4(wb[4], wb[5], wb[6], wb[7]);
        row[0] = lo; row[1] = hi;      // kt0 bits
        row[2] = lo; row[3] = hi;      // kt1 bits (same)
        float am = amask[tid];
        float* lb = reinterpret_cast<float*>(dyn + OFF_LB);
        lb[(tid >> 1) * 4 + (tid & 1)]     = lg2f(am);  // am=0 -> -inf -> f=0
        lb[(tid >> 1) * 4 + 2 + (tid & 1)] = consequent[tid * 17 + 16];
        reinterpret_cast<float*>(dyn + OFF_AM)[tid] = am;
    } else {
        const int r = tid - N_RULES;
        const float* cr = consequent + r * 17;
        uint32_t wb[8];
        #pragma unroll
        for (int i = 0; i < N_IN; i += 2)
            wb[i / 2] = pkhf(cr[i], cr[i + 1]);
        uint4* row = reinterpret_cast<uint4*>(dyn + OFF_BR + r * BR_STR);
        row[0] = make_uint4(wb[0], wb[1], wb[2], wb[3]);
        row[1] = make_uint4(wb[4], wb[5], wb[6], wb[7]);
    }
    __syncthreads();

    // ---- stage 3: MMA + fp32 epilogue, one 16-row slab at a time -----------
    const int q = lane >> 2;
    const int t = lane & 3;
    const uint32_t smBT = smA + OFF_BT;
    const uint32_t smBR = smA + OFF_BR;
    const float* sBase  = reinterpret_cast<const float*>(dyn + OFF_BASE);
    const float4* lb4   = reinterpret_cast<const float4*>(dyn + OFF_LB);
    const float2* am2   = reinterpret_cast<const float2*>(dyn + OFF_AM);

    float inv_den = 0.f;

    #pragma unroll
    for (int mt = 0; mt < 2; mt++) {
        const int R = warp * 32 + mt * 16;

        // A fragments for THIS slab only (12 regs live)
        uint32_t af[3][4];
        {
            int ar = R + (lane & 15);
            int ac0 = (lane >> 4) << 3;
            #pragma unroll
            for (int kt = 0; kt < 3; kt++)
                ldmx4(smA + ar * A_STR + (kt * 16 + ac0) * 2,
                      af[kt][0], af[kt][1], af[kt][2], af[kt][3]);
        }
        const float baseA = sBase[R + q];
        const float baseB = sBase[R + q + 8];

        float fsA = 0.f, accA = 0.f, fbaA = 0.f;
        float fsB = 0.f, accB = 0.f, fbaB = 0.f;
        float dsum = 0.f;

        #pragma unroll
        for (int nt = 0; nt < 8; nt++) {
            int brj = nt * 8 + (lane & 7);
            int bc0 = lane & 8;
            uint32_t bt[2][2], br[2];
            #pragma unroll
            for (int k = 0; k < 2; k++)
                ldmx2(smBT + brj * BT_STR + (k * 16 + bc0) * 2, bt[k][0], bt[k][1]);
            ldmx2(smBR + brj * BR_STR + bc0 * 2, br[0], br[1]);

            float4 lb = lb4[nt * 4 + t];        // (lam_e, lam_o, bias_e, bias_o)
            float2 av = am2[nt * 4 + t];
            dsum += av.x + av.y;

            float t0 = 0.f, t1 = 0.f, t2 = 0.f, t3 = 0.f;
            float r0 = 0.f, r1 = 0.f, r2 = 0.f, r3 = 0.f;
            #pragma unroll
            for (int k = 0; k < 2; k++)
                mma16816(t0, t1, t2, t3, af[k][0], af[k][1],
                         af[k][2], af[k][3], bt[k][0], bt[k][1]);
            mma16816(r0, r1, r2, r3, af[2][0], af[2][1],
                     af[2][2], af[2][3], br[0], br[1]);

            float ro0 = r0 + lb.z, ro1 = r1 + lb.w;
            float ro2 = r2 + lb.z, ro3 = r3 + lb.w;
            float f0 = ex2f(t0 + baseA + lb.x);
            float f1 = ex2f(t1 + baseA + lb.y);
            float f2 = ex2f(t2 + baseB + lb.x);
            float f3 = ex2f(t3 + baseB + lb.y);
            fsA += f0 + f1;
            accA = fmaf(f0, ro0, fmaf(f1, ro1, accA));
            fbaA = fmaf(av.x, ro0, fmaf(av.y, ro1, fbaA));
            fsB += f2 + f3;
            accB = fmaf(f2, ro2, fmaf(f3, ro3, accB));
            fbaB = fmaf(av.x, ro2, fmaf(av.y, ro3, fbaB));
        }

        if (mt == 0) {
            #pragma unroll
            for (int d = 1; d <= 2; d <<= 1)
                dsum += __shfl_xor_sync(0xffffffffu, dsum, d);
            inv_den = __fdividef(1.0f, fmaxf(dsum, 1.0f));
        }

        #pragma unroll
        for (int d = 1; d <= 2; d <<= 1) {
            fsA  += __shfl_xor_sync(0xffffffffu, fsA,  d);
            accA += __shfl_xor_sync(0xffffffffu, accA, d);
            fbaA += __shfl_xor_sync(0xffffffffu, fbaA, d);
            fsB  += __shfl_xor_sync(0xffffffffu, fsB,  d);
            accB += __shfl_xor_sync(0xffffffffu, accB, d);
            fbaB += __shfl_xor_sync(0xffffffffu, fbaB, d);
        }
        if (t == 0) {
            int rA = R + q, rB = R + q + 8;
            float zA = (fsA <= 1e-12f) ? (fbaA * inv_den) : __fdividef(accA, fsA);
            float zB = (fsB <= 1e-12f) ? (fbaB * inv_den) : __fdividef(accB, fsB);
            float sA = __fdividef(1.0f, 1.0f + ex2f(-zA * LOG2E));
            float sB = __fdividef(1.0f, 1.0f + ex2f(-zB * LOG2E));
            sA = fminf(fmaxf(sA, 1e-7f), 1.0f - 1e-7f);
            sB = fminf(fmaxf(sB, 1e-7f), 1.0f - 1e-7f);
            int gA = blockIdx.x * ROWS + rA;
            int gB = blockIdx.x * ROWS + rB;
            if (gA < B) out[gA] = sA;
            if (gB < B) out[gB] = sB;
        }
    }
}

extern "C" void kernel_launch(void* const* d_in, const int* in_sizes, int n_in,
                              void* d_out, int out_size)
{
    const float* x          = (const float*)d_in[0];
    const float* center     = (const float*)d_in[1];
    const float* log_sigma  = (const float*)d_in[2];
    const float* consequent = (const float*)d_in[3];
    const int*   rule_idx   = (const int*)  d_in[4];
    const float* amask      = (const float*)d_in[5];
    float*       out        = (float*)d_out;

    int B = in_sizes[0] / N_IN;
    int grid = (B + ROWS - 1) / ROWS;

    anfis_mma<<<grid, TPB, SM_TOTAL>>>(x, center, log_sigma, consequent,
                                       rule_idx, amask, out, B);
}